// round 12
// baseline (speedup 1.0000x reference)
#include <cuda_runtime.h>
#include <cuda_fp16.h>
#include <cstdint>

// Problem constants (fixed shapes for this dataset)
#define BB   4
#define NN   50000
#define CIN  64
#define EE   800000
#define HALF 32
#define BN   (BB * NN)           // 200000

#define HIST_BLOCKS  782         // ceil(EE/4 / 256), 4 edges/thread
#define PROJ_BLOCKS  1563        // ceil(NN / 32)
#define CAP  64                  // padded-CSR slots per node (max degree ~40)

// ---------------- scratch (device globals; zero-initialized at load) --------
__device__ __half g_hlin[NN * 128];    // [n][ch][b]  half, 12.8 MB (L2-resident)
__device__ int    g_counts[NN];        // kept zero between calls (gather re-zeros)
__device__ int2   g_csrp[NN * CAP];    // padded CSR: .x = col, .y = bits(val)

// ---------------- mma / f32x2 helpers ---------------------------------------
__device__ __forceinline__ void mma16816(float& d0, float& d1, float& d2, float& d3,
                                         unsigned a0, unsigned a1, unsigned a2, unsigned a3,
                                         unsigned b0, unsigned b1) {
    asm("mma.sync.aligned.m16n8k16.row.col.f32.f16.f16.f32 "
        "{%0,%1,%2,%3}, {%4,%5,%6,%7}, {%8,%9}, {%0,%1,%2,%3};"
        : "+f"(d0), "+f"(d1), "+f"(d2), "+f"(d3)
        : "r"(a0), "r"(a1), "r"(a2), "r"(a3), "r"(b0), "r"(b1));
}
__device__ __forceinline__ void ffma2(unsigned long long& d,
                                      unsigned long long a,
                                      unsigned long long b) {
    asm("fma.rn.f32x2 %0, %1, %2, %0;" : "+l"(d) : "l"(a), "l"(b));
}
__device__ __forceinline__ unsigned long long dup2(float v) {
    unsigned long long d;
    unsigned u = __float_as_uint(v);
    asm("mov.b64 %0, {%1, %1};" : "=l"(d) : "r"(u));
    return d;
}
__device__ __forceinline__ float lo32(unsigned long long v) {
    return __uint_as_float((unsigned)v);
}
__device__ __forceinline__ float hi32(unsigned long long v) {
    return __uint_as_float((unsigned)(v >> 32));
}

// ---------------- K1: HMMA projection + fused hist-scatter -------------------
// proj tile: 32 nodes x 4 batches (128 A-rows) x 64 outs; 256 threads, 8 warps.
#define XS_STRIDE 72    // halves; frag LDS bank = 4g+tig, conflict-free
#define SL_STRIDE 132   // halves per node in slin
#define SE_STRIDE 34    // floats per row in seye
#define SMEM_BYTES 28672

__global__ __launch_bounds__(256, 3) void k1_proj_histscat_kernel(
    const int4*   __restrict__ rows4,
    const int4*   __restrict__ cols4,
    const float4* __restrict__ vals4,
    const float*  __restrict__ x,
    const float*  __restrict__ Wlin,
    const float*  __restrict__ Weye,
    const float*  __restrict__ beye,
    float*        __restrict__ out)
{
    __shared__ __align__(16) char sm[SMEM_BYTES];
    const int tid = threadIdx.x;

    if (blockIdx.x >= PROJ_BLOCKS) {
        // ---- hist + direct padded-CSR scatter: 4 edges / thread ----
        int i = (blockIdx.x - PROJ_BLOCKS) * 256 + tid;
        if (i < EE / 4) {
            int4   r = rows4[i];
            int4   c = cols4[i];
            float4 v = vals4[i];
            int k;
            k = atomicAdd(&g_counts[r.x], 1);
            if (k < CAP) g_csrp[(r.x << 6) + k] = make_int2(c.x, __float_as_int(v.x));
            k = atomicAdd(&g_counts[r.y], 1);
            if (k < CAP) g_csrp[(r.y << 6) + k] = make_int2(c.y, __float_as_int(v.y));
            k = atomicAdd(&g_counts[r.z], 1);
            if (k < CAP) g_csrp[(r.z << 6) + k] = make_int2(c.z, __float_as_int(v.z));
            k = atomicAdd(&g_counts[r.w], 1);
            if (k < CAP) g_csrp[(r.w << 6) + k] = make_int2(c.w, __float_as_int(v.w));
        }
        return;
    }

    // ---- projection ----
    __half* xs = (__half*)sm;                          // [128][XS_STRIDE]
    __half* wt = (__half*)(sm + 128 * XS_STRIDE * 2);  // [64][XS_STRIDE]

    const int node0 = blockIdx.x * 32;

    // Stage x (128 rows = 4b x 32 nodes, 64 ch) + W^T (64 n x 64 k) as fp16.
    #pragma unroll
    for (int it = 0; it < 12; ++it) {
        int idx = tid + it * 256;                   // 0..3071
        if (idx < 2048) {
            int row = idx >> 4;                     // 0..127
            int c4  = (idx & 15) << 2;
            int b   = row >> 5;
            int node = row & 31;
            int nn  = node0 + node; if (nn >= NN) nn = NN - 1;
            float4 v = *(const float4*)(x + ((size_t)(b * NN + nn)) * 64 + c4);
            *(__half2*)&xs[row * XS_STRIDE + c4]     = __floats2half2_rn(v.x, v.y);
            *(__half2*)&xs[row * XS_STRIDE + c4 + 2] = __floats2half2_rn(v.z, v.w);
        } else {
            int id2 = idx - 2048;                   // 0..1023
            int row = id2 >> 4;                     // 0..63
            int c4  = (id2 & 15) << 2;
            const float* wsrc = (row < 32) ? (Wlin + row * 64 + c4)
                                           : (Weye + (row - 32) * 64 + c4);
            float4 w = *(const float4*)wsrc;
            *(__half2*)&wt[row * XS_STRIDE + c4]     = __floats2half2_rn(w.x, w.y);
            *(__half2*)&wt[row * XS_STRIDE + c4 + 2] = __floats2half2_rn(w.z, w.w);
        }
    }
    __syncthreads();

    const int warp = tid >> 5;
    const int lane = tid & 31;
    const int g    = lane >> 2;        // 0..7
    const int tig  = lane & 3;         // 0..3
    const int wrow = warp * 16;        // warp's A-row base

    float d[8][4];
    #pragma unroll
    for (int nf = 0; nf < 8; ++nf)
        #pragma unroll
        for (int k = 0; k < 4; ++k) d[nf][k] = 0.f;

    #pragma unroll
    for (int kc = 0; kc < 4; ++kc) {
        const int kb = kc * 16;
        unsigned a0 = *(const unsigned*)&xs[(wrow + g)     * XS_STRIDE + kb + 2 * tig];
        unsigned a1 = *(const unsigned*)&xs[(wrow + g + 8) * XS_STRIDE + kb + 2 * tig];
        unsigned a2 = *(const unsigned*)&xs[(wrow + g)     * XS_STRIDE + kb + 2 * tig + 8];
        unsigned a3 = *(const unsigned*)&xs[(wrow + g + 8) * XS_STRIDE + kb + 2 * tig + 8];
        #pragma unroll
        for (int nf = 0; nf < 8; ++nf) {
            unsigned b0 = *(const unsigned*)&wt[(nf * 8 + g) * XS_STRIDE + kb + 2 * tig];
            unsigned b1 = *(const unsigned*)&wt[(nf * 8 + g) * XS_STRIDE + kb + 2 * tig + 8];
            mma16816(d[nf][0], d[nf][1], d[nf][2], d[nf][3],
                     a0, a1, a2, a3, b0, b1);
        }
    }

    // biases for eye columns (2 per frag)
    float be[4][2];
    #pragma unroll
    for (int nf = 4; nf < 8; ++nf) {
        int oc = nf * 8 + 2 * tig - 32;
        be[nf - 4][0] = __ldg(&beye[oc]);
        be[nf - 4][1] = __ldg(&beye[oc + 1]);
    }

    __syncthreads();   // done reading xs/wt; reuse smem for output staging

    __half* slin = (__half*)sm;                        // [32][SL_STRIDE] halves
    float*  seye = (float*)(sm + 32 * SL_STRIDE * 2);  // [128][SE_STRIDE] floats

    const int b        = warp >> 1;            // batch this warp owns
    const int nodeBase = (warp & 1) * 16;

    #pragma unroll
    for (int h2 = 0; h2 < 2; ++h2) {
        int node = nodeBase + g + 8 * h2;
        int r    = wrow + g + 8 * h2;          // tile row = 32*b + node
        #pragma unroll
        for (int nf = 0; nf < 4; ++nf) {
            int ch = nf * 8 + 2 * tig;
            float v0 = h2 ? d[nf][2] : d[nf][0];
            float v1 = h2 ? d[nf][3] : d[nf][1];
            slin[node * SL_STRIDE + ch * 4 + b]       = __float2half_rn(v0);
            slin[node * SL_STRIDE + (ch + 1) * 4 + b] = __float2half_rn(v1);
        }
        #pragma unroll
        for (int nf = 4; nf < 8; ++nf) {
            int c = (nf - 4) * 8 + 2 * tig;
            float v0 = (h2 ? d[nf][2] : d[nf][0]) + be[nf - 4][0];
            float v1 = (h2 ? d[nf][3] : d[nf][1]) + be[nf - 4][1];
            seye[r * SE_STRIDE + c]     = v0;
            seye[r * SE_STRIDE + c + 1] = v1;
        }
    }
    __syncthreads();

    // cooperative coalesced writes
    #pragma unroll
    for (int it = 0; it < 4; ++it) {
        int idx  = tid + it * 256;             // 0..1023
        int node = idx >> 5;
        int q    = idx & 31;
        int n    = node0 + node;
        if (n < NN) {
            uint2 v = *(const uint2*)&slin[node * SL_STRIDE + q * 4];
            *(uint2*)&g_hlin[(size_t)n * 128 + q * 4] = v;
        }
    }
    #pragma unroll
    for (int it = 0; it < 8; ++it) {
        int idx = tid + it * 256;              // 0..2047
        int row = idx >> 4;
        int q   = idx & 15;
        int bb  = row >> 5;
        int node = row & 31;
        int n   = node0 + node;
        if (n < NN) {
            float2 v = *(const float2*)&seye[row * SE_STRIDE + q * 2];
            *(float2*)&out[((size_t)bb * NN + n) * 64 + 32 + q * 2] = v;
        }
    }
}

// ---------------- gather: one warp per node, padded CSR, f32x2 FMAs ---------
__global__ __launch_bounds__(256) void gather_kernel(const float* __restrict__ blin,
                                                     float* __restrict__ out) {
    int n    = (blockIdx.x * blockDim.x + threadIdx.x) >> 5;
    int lane = threadIdx.x & 31;
    if (n >= NN) return;

    int cnt = g_counts[n];
    if (lane == 0) g_counts[n] = 0;        // reset for the next invocation
    int s = n << 6;
    int t = s + (cnt < CAP ? cnt : CAP);

    unsigned long long A01 = 0ull, A23 = 0ull;   // packed f32 accum (b0,b1),(b2,b3)
    int e = s;
    for (; e + 4 <= t; e += 4) {
        int2 p0 = g_csrp[e];
        int2 p1 = g_csrp[e + 1];
        int2 p2 = g_csrp[e + 2];
        int2 p3 = g_csrp[e + 3];
        uint2 q0 = *(const uint2*)(g_hlin + (size_t)p0.x * 128 + lane * 4);
        uint2 q1 = *(const uint2*)(g_hlin + (size_t)p1.x * 128 + lane * 4);
        uint2 q2 = *(const uint2*)(g_hlin + (size_t)p2.x * 128 + lane * 4);
        uint2 q3 = *(const uint2*)(g_hlin + (size_t)p3.x * 128 + lane * 4);
        {
            float2 u01 = __half22float2(*(__half2*)&q0.x);
            float2 u23 = __half22float2(*(__half2*)&q0.y);
            unsigned long long sv = dup2(__int_as_float(p0.y));
            ffma2(A01, sv, *(unsigned long long*)&u01);
            ffma2(A23, sv, *(unsigned long long*)&u23);
        }
        {
            float2 u01 = __half22float2(*(__half2*)&q1.x);
            float2 u23 = __half22float2(*(__half2*)&q1.y);
            unsigned long long sv = dup2(__int_as_float(p1.y));
            ffma2(A01, sv, *(unsigned long long*)&u01);
            ffma2(A23, sv, *(unsigned long long*)&u23);
        }
        {
            float2 u01 = __half22float2(*(__half2*)&q2.x);
            float2 u23 = __half22float2(*(__half2*)&q2.y);
            unsigned long long sv = dup2(__int_as_float(p2.y));
            ffma2(A01, sv, *(unsigned long long*)&u01);
            ffma2(A23, sv, *(unsigned long long*)&u23);
        }
        {
            float2 u01 = __half22float2(*(__half2*)&q3.x);
            float2 u23 = __half22float2(*(__half2*)&q3.y);
            unsigned long long sv = dup2(__int_as_float(p3.y));
            ffma2(A01, sv, *(unsigned long long*)&u01);
            ffma2(A23, sv, *(unsigned long long*)&u23);
        }
    }
    for (; e < t; ++e) {
        int2 p = g_csrp[e];
        uint2 q = *(const uint2*)(g_hlin + (size_t)p.x * 128 + lane * 4);
        float2 u01 = __half22float2(*(__half2*)&q.x);
        float2 u23 = __half22float2(*(__half2*)&q.y);
        unsigned long long sv = dup2(__int_as_float(p.y));
        ffma2(A01, sv, *(unsigned long long*)&u01);
        ffma2(A23, sv, *(unsigned long long*)&u23);
    }

    float bl = blin[lane];
    out[((size_t)0 * NN + n) * 64 + lane] = lo32(A01) + bl;
    out[((size_t)1 * NN + n) * 64 + lane] = hi32(A01) + bl;
    out[((size_t)2 * NN + n) * 64 + lane] = lo32(A23) + bl;
    out[((size_t)3 * NN + n) * 64 + lane] = hi32(A23) + bl;
}

// ---------------- launch: single stream, 2 kernels ---------------------------
extern "C" void kernel_launch(void* const* d_in, const int* in_sizes, int n_in,
                              void* d_out, int out_size) {
    const float* x    = (const float*)d_in[0];
    const float* vals = (const float*)d_in[1];
    const float* Wlin = (const float*)d_in[2];
    const float* blin = (const float*)d_in[3];
    const float* Weye = (const float*)d_in[4];
    const float* beye = (const float*)d_in[5];
    const int*   rows = (const int*)d_in[6];
    const int*   cols = (const int*)d_in[7];
    float* out = (float*)d_out;
    (void)in_sizes; (void)n_in; (void)out_size;

    // g_counts is zero on entry (zero-init at load; gather re-zeros each call)
    k1_proj_histscat_kernel<<<PROJ_BLOCKS + HIST_BLOCKS, 256>>>(
        (const int4*)rows, (const int4*)cols, (const float4*)vals,
        x, Wlin, Weye, beye, out);
    gather_kernel<<<(NN * 32 + 255) / 256, 256>>>(blin, out);
}

// round 13
// speedup vs baseline: 1.0176x; 1.0176x over previous
#include <cuda_runtime.h>
#include <cuda_fp16.h>
#include <cstdint>

// Problem constants (fixed shapes for this dataset)
#define BB   4
#define NN   50000
#define CIN  64
#define EE   800000
#define HALF 32
#define BN   (BB * NN)           // 200000

#define HIST_BLOCKS  782         // ceil(EE/4 / 256), 4 edges/thread
#define PROJ_BLOCKS  1563        // ceil(NN / 32)
#define CAP  64                  // padded-CSR slots per node (max degree ~40)

// ---------------- scratch (device globals; zero-initialized at load) --------
__device__ __half g_hlin[NN * 128];    // [n][ch][b]  half, 12.8 MB (L2-resident)
__device__ int    g_counts[NN];        // kept zero between calls (gather re-zeros)
__device__ int2   g_csrp[NN * CAP];    // padded CSR: .x = col, .y = bits(val)

// ---------------- mma helper -------------------------------------------------
__device__ __forceinline__ void mma16816(float& d0, float& d1, float& d2, float& d3,
                                         unsigned a0, unsigned a1, unsigned a2, unsigned a3,
                                         unsigned b0, unsigned b1) {
    asm("mma.sync.aligned.m16n8k16.row.col.f32.f16.f16.f32 "
        "{%0,%1,%2,%3}, {%4,%5,%6,%7}, {%8,%9}, {%0,%1,%2,%3};"
        : "+f"(d0), "+f"(d1), "+f"(d2), "+f"(d3)
        : "r"(a0), "r"(a1), "r"(a2), "r"(a3), "r"(b0), "r"(b1));
}

// ---------------- K1: HMMA projection + fused hist-scatter -------------------
// proj tile: 32 nodes x 4 batches (128 A-rows) x 64 outs; 256 threads, 8 warps.
#define XS_STRIDE 72    // halves; frag LDS bank = 4g+tig, conflict-free
#define SL_STRIDE 132   // halves per node in slin
#define SE_STRIDE 34    // floats per row in seye
#define SMEM_BYTES 28672

__global__ __launch_bounds__(256, 3) void k1_proj_histscat_kernel(
    const int4*   __restrict__ rows4,
    const int4*   __restrict__ cols4,
    const float4* __restrict__ vals4,
    const float*  __restrict__ x,
    const float*  __restrict__ Wlin,
    const float*  __restrict__ Weye,
    const float*  __restrict__ beye,
    float*        __restrict__ out)
{
    __shared__ __align__(16) char sm[SMEM_BYTES];
    const int tid = threadIdx.x;

    if (blockIdx.x >= PROJ_BLOCKS) {
        // ---- hist + direct padded-CSR scatter: 4 edges / thread ----
        int i = (blockIdx.x - PROJ_BLOCKS) * 256 + tid;
        if (i < EE / 4) {
            int4   r = rows4[i];
            int4   c = cols4[i];
            float4 v = vals4[i];
            int k;
            k = atomicAdd(&g_counts[r.x], 1);
            if (k < CAP) g_csrp[(r.x << 6) + k] = make_int2(c.x, __float_as_int(v.x));
            k = atomicAdd(&g_counts[r.y], 1);
            if (k < CAP) g_csrp[(r.y << 6) + k] = make_int2(c.y, __float_as_int(v.y));
            k = atomicAdd(&g_counts[r.z], 1);
            if (k < CAP) g_csrp[(r.z << 6) + k] = make_int2(c.z, __float_as_int(v.z));
            k = atomicAdd(&g_counts[r.w], 1);
            if (k < CAP) g_csrp[(r.w << 6) + k] = make_int2(c.w, __float_as_int(v.w));
        }
        return;
    }

    // ---- projection ----
    __half* xs = (__half*)sm;                          // [128][XS_STRIDE]
    __half* wt = (__half*)(sm + 128 * XS_STRIDE * 2);  // [64][XS_STRIDE]

    const int node0 = blockIdx.x * 32;

    // Stage x (128 rows = 4b x 32 nodes, 64 ch) + W^T (64 n x 64 k) as fp16.
    #pragma unroll
    for (int it = 0; it < 12; ++it) {
        int idx = tid + it * 256;                   // 0..3071
        if (idx < 2048) {
            int row = idx >> 4;                     // 0..127
            int c4  = (idx & 15) << 2;
            int b   = row >> 5;
            int node = row & 31;
            int nn  = node0 + node; if (nn >= NN) nn = NN - 1;
            float4 v = *(const float4*)(x + ((size_t)(b * NN + nn)) * 64 + c4);
            *(__half2*)&xs[row * XS_STRIDE + c4]     = __floats2half2_rn(v.x, v.y);
            *(__half2*)&xs[row * XS_STRIDE + c4 + 2] = __floats2half2_rn(v.z, v.w);
        } else {
            int id2 = idx - 2048;                   // 0..1023
            int row = id2 >> 4;                     // 0..63
            int c4  = (id2 & 15) << 2;
            const float* wsrc = (row < 32) ? (Wlin + row * 64 + c4)
                                           : (Weye + (row - 32) * 64 + c4);
            float4 w = *(const float4*)wsrc;
            *(__half2*)&wt[row * XS_STRIDE + c4]     = __floats2half2_rn(w.x, w.y);
            *(__half2*)&wt[row * XS_STRIDE + c4 + 2] = __floats2half2_rn(w.z, w.w);
        }
    }
    __syncthreads();

    const int warp = tid >> 5;
    const int lane = tid & 31;
    const int g    = lane >> 2;        // 0..7
    const int tig  = lane & 3;         // 0..3
    const int wrow = warp * 16;        // warp's A-row base

    float d[8][4];
    #pragma unroll
    for (int nf = 0; nf < 8; ++nf)
        #pragma unroll
        for (int k = 0; k < 4; ++k) d[nf][k] = 0.f;

    #pragma unroll
    for (int kc = 0; kc < 4; ++kc) {
        const int kb = kc * 16;
        unsigned a0 = *(const unsigned*)&xs[(wrow + g)     * XS_STRIDE + kb + 2 * tig];
        unsigned a1 = *(const unsigned*)&xs[(wrow + g + 8) * XS_STRIDE + kb + 2 * tig];
        unsigned a2 = *(const unsigned*)&xs[(wrow + g)     * XS_STRIDE + kb + 2 * tig + 8];
        unsigned a3 = *(const unsigned*)&xs[(wrow + g + 8) * XS_STRIDE + kb + 2 * tig + 8];
        #pragma unroll
        for (int nf = 0; nf < 8; ++nf) {
            unsigned b0 = *(const unsigned*)&wt[(nf * 8 + g) * XS_STRIDE + kb + 2 * tig];
            unsigned b1 = *(const unsigned*)&wt[(nf * 8 + g) * XS_STRIDE + kb + 2 * tig + 8];
            mma16816(d[nf][0], d[nf][1], d[nf][2], d[nf][3],
                     a0, a1, a2, a3, b0, b1);
        }
    }

    // biases for eye columns (2 per frag)
    float be[4][2];
    #pragma unroll
    for (int nf = 4; nf < 8; ++nf) {
        int oc = nf * 8 + 2 * tig - 32;
        be[nf - 4][0] = __ldg(&beye[oc]);
        be[nf - 4][1] = __ldg(&beye[oc + 1]);
    }

    __syncthreads();   // done reading xs/wt; reuse smem for output staging

    __half* slin = (__half*)sm;                        // [32][SL_STRIDE] halves
    float*  seye = (float*)(sm + 32 * SL_STRIDE * 2);  // [128][SE_STRIDE] floats

    const int b        = warp >> 1;            // batch this warp owns
    const int nodeBase = (warp & 1) * 16;

    #pragma unroll
    for (int h2 = 0; h2 < 2; ++h2) {
        int node = nodeBase + g + 8 * h2;
        int r    = wrow + g + 8 * h2;          // tile row = 32*b + node
        #pragma unroll
        for (int nf = 0; nf < 4; ++nf) {
            int ch = nf * 8 + 2 * tig;
            float v0 = h2 ? d[nf][2] : d[nf][0];
            float v1 = h2 ? d[nf][3] : d[nf][1];
            slin[node * SL_STRIDE + ch * 4 + b]       = __float2half_rn(v0);
            slin[node * SL_STRIDE + (ch + 1) * 4 + b] = __float2half_rn(v1);
        }
        #pragma unroll
        for (int nf = 4; nf < 8; ++nf) {
            int c = (nf - 4) * 8 + 2 * tig;
            float v0 = (h2 ? d[nf][2] : d[nf][0]) + be[nf - 4][0];
            float v1 = (h2 ? d[nf][3] : d[nf][1]) + be[nf - 4][1];
            seye[r * SE_STRIDE + c]     = v0;
            seye[r * SE_STRIDE + c + 1] = v1;
        }
    }
    __syncthreads();

    // cooperative coalesced writes
    #pragma unroll
    for (int it = 0; it < 4; ++it) {
        int idx  = tid + it * 256;             // 0..1023
        int node = idx >> 5;
        int q    = idx & 31;
        int n    = node0 + node;
        if (n < NN) {
            uint2 v = *(const uint2*)&slin[node * SL_STRIDE + q * 4];
            *(uint2*)&g_hlin[(size_t)n * 128 + q * 4] = v;
        }
    }
    #pragma unroll
    for (int it = 0; it < 8; ++it) {
        int idx = tid + it * 256;              // 0..2047
        int row = idx >> 4;
        int q   = idx & 15;
        int bb  = row >> 5;
        int node = row & 31;
        int n   = node0 + node;
        if (n < NN) {
            float2 v = *(const float2*)&seye[row * SE_STRIDE + q * 2];
            *(float2*)&out[((size_t)bb * NN + n) * 64 + 32 + q * 2] = v;
        }
    }
}

// ---------------- gather: one warp per node, padded CSR, scalar FMAs ---------
__global__ __launch_bounds__(256) void gather_kernel(const float* __restrict__ blin,
                                                     float* __restrict__ out) {
    int n    = (blockIdx.x * blockDim.x + threadIdx.x) >> 5;
    int lane = threadIdx.x & 31;
    if (n >= NN) return;

    int cnt = g_counts[n];
    if (lane == 0) g_counts[n] = 0;        // reset for the next invocation
    int s = n << 6;
    int t = s + (cnt < CAP ? cnt : CAP);

    float a0 = 0.f, a1 = 0.f, a2 = 0.f, a3 = 0.f;
    int e = s;
    for (; e + 4 <= t; e += 4) {
        int2 p0 = g_csrp[e];
        int2 p1 = g_csrp[e + 1];
        int2 p2 = g_csrp[e + 2];
        int2 p3 = g_csrp[e + 3];
        uint2 q0 = *(const uint2*)(g_hlin + (size_t)p0.x * 128 + lane * 4);
        uint2 q1 = *(const uint2*)(g_hlin + (size_t)p1.x * 128 + lane * 4);
        uint2 q2 = *(const uint2*)(g_hlin + (size_t)p2.x * 128 + lane * 4);
        uint2 q3 = *(const uint2*)(g_hlin + (size_t)p3.x * 128 + lane * 4);
        float s0 = __int_as_float(p0.y), s1 = __int_as_float(p1.y);
        float s2 = __int_as_float(p2.y), s3 = __int_as_float(p3.y);
        float2 u01, u23;
        u01 = __half22float2(*(__half2*)&q0.x); u23 = __half22float2(*(__half2*)&q0.y);
        a0 += s0 * u01.x; a1 += s0 * u01.y; a2 += s0 * u23.x; a3 += s0 * u23.y;
        u01 = __half22float2(*(__half2*)&q1.x); u23 = __half22float2(*(__half2*)&q1.y);
        a0 += s1 * u01.x; a1 += s1 * u01.y; a2 += s1 * u23.x; a3 += s1 * u23.y;
        u01 = __half22float2(*(__half2*)&q2.x); u23 = __half22float2(*(__half2*)&q2.y);
        a0 += s2 * u01.x; a1 += s2 * u01.y; a2 += s2 * u23.x; a3 += s2 * u23.y;
        u01 = __half22float2(*(__half2*)&q3.x); u23 = __half22float2(*(__half2*)&q3.y);
        a0 += s3 * u01.x; a1 += s3 * u01.y; a2 += s3 * u23.x; a3 += s3 * u23.y;
    }
    for (; e < t; ++e) {
        int2 p = g_csrp[e];
        uint2 q = *(const uint2*)(g_hlin + (size_t)p.x * 128 + lane * 4);
        float sv = __int_as_float(p.y);
        float2 u01 = __half22float2(*(__half2*)&q.x);
        float2 u23 = __half22float2(*(__half2*)&q.y);
        a0 += sv * u01.x; a1 += sv * u01.y; a2 += sv * u23.x; a3 += sv * u23.y;
    }

    float bl = blin[lane];
    out[((size_t)0 * NN + n) * 64 + lane] = a0 + bl;
    out[((size_t)1 * NN + n) * 64 + lane] = a1 + bl;
    out[((size_t)2 * NN + n) * 64 + lane] = a2 + bl;
    out[((size_t)3 * NN + n) * 64 + lane] = a3 + bl;
}

// ---------------- launch: single stream, 2 kernels ---------------------------
extern "C" void kernel_launch(void* const* d_in, const int* in_sizes, int n_in,
                              void* d_out, int out_size) {
    const float* x    = (const float*)d_in[0];
    const float* vals = (const float*)d_in[1];
    const float* Wlin = (const float*)d_in[2];
    const float* blin = (const float*)d_in[3];
    const float* Weye = (const float*)d_in[4];
    const float* beye = (const float*)d_in[5];
    const int*   rows = (const int*)d_in[6];
    const int*   cols = (const int*)d_in[7];
    float* out = (float*)d_out;
    (void)in_sizes; (void)n_in; (void)out_size;

    // g_counts is zero on entry (zero-init at load; gather re-zeros each call)
    k1_proj_histscat_kernel<<<PROJ_BLOCKS + HIST_BLOCKS, 256>>>(
        (const int4*)rows, (const int4*)cols, (const float4*)vals,
        x, Wlin, Weye, beye, out);
    gather_kernel<<<(NN * 32 + 255) / 256, 256>>>(blin, out);
}

// round 14
// speedup vs baseline: 1.9466x; 1.9129x over previous
#include <cuda_runtime.h>
#include <cuda_fp16.h>
#include <cstdint>

// Problem constants (fixed shapes for this dataset)
#define BB   4
#define NN   50000
#define CIN  64
#define EE   800000
#define HALF 32
#define BN   (BB * NN)           // 200000

#define HIST_BLOCKS  782         // ceil(EE/4 / 256), 4 edges/thread
#define SCAT_BLOCKS  391         // ceil(EE/8 / 256), 8 edges/thread
#define PROJ_BLOCKS  1563        // ceil(NN / 32)
#define NCHUNK       49          // ceil(NN/1024)

// ---------------- scratch (device globals; zero-initialized at load) --------
__device__ __half g_hlin[NN * 128];    // [n][ch][b]  half, 12.8 MB (L2-resident)
__device__ int    g_counts[NN];        // kept zero between calls (scanB re-zeros)
__device__ int    g_offsets[NN + 1];
__device__ int    g_rank[EE];          // within-node rank of each edge
__device__ int2   g_csr[EE];           // .x = col, .y = bits(val)
__device__ int    g_blocksums[64];     // kept zero between calls (scatter re-zeros)

// ---------------- mma helper -------------------------------------------------
__device__ __forceinline__ void mma16816(float& d0, float& d1, float& d2, float& d3,
                                         unsigned a0, unsigned a1, unsigned a2, unsigned a3,
                                         unsigned b0, unsigned b1) {
    asm("mma.sync.aligned.m16n8k16.row.col.f32.f16.f16.f32 "
        "{%0,%1,%2,%3}, {%4,%5,%6,%7}, {%8,%9}, {%0,%1,%2,%3};"
        : "+f"(d0), "+f"(d1), "+f"(d2), "+f"(d3)
        : "r"(a0), "r"(a1), "r"(a2), "r"(a3), "r"(b0), "r"(b1));
}

// ---------------- K1: HMMA projection + histogram (block-range fused) --------
// proj tile: 32 nodes x 4 batches (128 A-rows) x 64 outs; 256 threads, 8 warps.
#define XS_STRIDE 72    // halves; frag LDS bank = 4g+tig, conflict-free
#define SL_STRIDE 132   // halves per node in slin
#define SE_STRIDE 34    // floats per row in seye
#define SMEM_BYTES 28672

__global__ __launch_bounds__(256, 3) void k1_proj_hist_kernel(
    const int4*  __restrict__ rows4,
    const float* __restrict__ x,
    const float* __restrict__ Wlin,
    const float* __restrict__ Weye,
    const float* __restrict__ beye,
    float*       __restrict__ out)
{
    __shared__ __align__(16) char sm[SMEM_BYTES];
    const int tid = threadIdx.x;

    if (blockIdx.x >= PROJ_BLOCKS) {
        // ---- histogram + rank recording + chunk sums ----
        int* sh = (int*)sm;
        if (tid < NCHUNK) sh[tid] = 0;
        __syncthreads();

        int i = (blockIdx.x - PROJ_BLOCKS) * 256 + tid;
        if (i < EE / 4) {
            int4 r = rows4[i];
            int4 rk;
            rk.x = atomicAdd(&g_counts[r.x], 1); atomicAdd(&sh[r.x >> 10], 1);
            rk.y = atomicAdd(&g_counts[r.y], 1); atomicAdd(&sh[r.y >> 10], 1);
            rk.z = atomicAdd(&g_counts[r.z], 1); atomicAdd(&sh[r.z >> 10], 1);
            rk.w = atomicAdd(&g_counts[r.w], 1); atomicAdd(&sh[r.w >> 10], 1);
            ((int4*)g_rank)[i] = rk;
        }
        __syncthreads();
        if (tid < NCHUNK && sh[tid]) atomicAdd(&g_blocksums[tid], sh[tid]);
        return;
    }

    // ---- projection ----
    __half* xs = (__half*)sm;                          // [128][XS_STRIDE]
    __half* wt = (__half*)(sm + 128 * XS_STRIDE * 2);  // [64][XS_STRIDE]

    const int node0 = blockIdx.x * 32;

    // Stage x (128 rows = 4b x 32 nodes, 64 ch) + W^T (64 n x 64 k) as fp16.
    // x is read exactly once per call -> streaming loads (evict-first).
    #pragma unroll
    for (int it = 0; it < 12; ++it) {
        int idx = tid + it * 256;                   // 0..3071
        if (idx < 2048) {
            int row = idx >> 4;                     // 0..127
            int c4  = (idx & 15) << 2;
            int b   = row >> 5;
            int node = row & 31;
            int nn  = node0 + node; if (nn >= NN) nn = NN - 1;
            float4 v = __ldcs((const float4*)(x + ((size_t)(b * NN + nn)) * 64 + c4));
            *(__half2*)&xs[row * XS_STRIDE + c4]     = __floats2half2_rn(v.x, v.y);
            *(__half2*)&xs[row * XS_STRIDE + c4 + 2] = __floats2half2_rn(v.z, v.w);
        } else {
            int id2 = idx - 2048;                   // 0..1023
            int row = id2 >> 4;                     // 0..63
            int c4  = (id2 & 15) << 2;
            const float* wsrc = (row < 32) ? (Wlin + row * 64 + c4)
                                           : (Weye + (row - 32) * 64 + c4);
            float4 w = *(const float4*)wsrc;
            *(__half2*)&wt[row * XS_STRIDE + c4]     = __floats2half2_rn(w.x, w.y);
            *(__half2*)&wt[row * XS_STRIDE + c4 + 2] = __floats2half2_rn(w.z, w.w);
        }
    }
    __syncthreads();

    const int warp = tid >> 5;
    const int lane = tid & 31;
    const int g    = lane >> 2;        // 0..7
    const int tig  = lane & 3;         // 0..3
    const int wrow = warp * 16;        // warp's A-row base

    float d[8][4];
    #pragma unroll
    for (int nf = 0; nf < 8; ++nf)
        #pragma unroll
        for (int k = 0; k < 4; ++k) d[nf][k] = 0.f;

    #pragma unroll
    for (int kc = 0; kc < 4; ++kc) {
        const int kb = kc * 16;
        unsigned a0 = *(const unsigned*)&xs[(wrow + g)     * XS_STRIDE + kb + 2 * tig];
        unsigned a1 = *(const unsigned*)&xs[(wrow + g + 8) * XS_STRIDE + kb + 2 * tig];
        unsigned a2 = *(const unsigned*)&xs[(wrow + g)     * XS_STRIDE + kb + 2 * tig + 8];
        unsigned a3 = *(const unsigned*)&xs[(wrow + g + 8) * XS_STRIDE + kb + 2 * tig + 8];
        #pragma unroll
        for (int nf = 0; nf < 8; ++nf) {
            unsigned b0 = *(const unsigned*)&wt[(nf * 8 + g) * XS_STRIDE + kb + 2 * tig];
            unsigned b1 = *(const unsigned*)&wt[(nf * 8 + g) * XS_STRIDE + kb + 2 * tig + 8];
            mma16816(d[nf][0], d[nf][1], d[nf][2], d[nf][3],
                     a0, a1, a2, a3, b0, b1);
        }
    }

    // biases for eye columns (2 per frag)
    float be[4][2];
    #pragma unroll
    for (int nf = 4; nf < 8; ++nf) {
        int oc = nf * 8 + 2 * tig - 32;
        be[nf - 4][0] = __ldg(&beye[oc]);
        be[nf - 4][1] = __ldg(&beye[oc + 1]);
    }

    __syncthreads();   // done reading xs/wt; reuse smem for output staging

    __half* slin = (__half*)sm;                        // [32][SL_STRIDE] halves
    float*  seye = (float*)(sm + 32 * SL_STRIDE * 2);  // [128][SE_STRIDE] floats

    const int b        = warp >> 1;            // batch this warp owns
    const int nodeBase = (warp & 1) * 16;

    #pragma unroll
    for (int h2 = 0; h2 < 2; ++h2) {
        int node = nodeBase + g + 8 * h2;
        int r    = wrow + g + 8 * h2;          // tile row = 32*b + node
        #pragma unroll
        for (int nf = 0; nf < 4; ++nf) {
            int ch = nf * 8 + 2 * tig;
            float v0 = h2 ? d[nf][2] : d[nf][0];
            float v1 = h2 ? d[nf][3] : d[nf][1];
            slin[node * SL_STRIDE + ch * 4 + b]       = __float2half_rn(v0);
            slin[node * SL_STRIDE + (ch + 1) * 4 + b] = __float2half_rn(v1);
        }
        #pragma unroll
        for (int nf = 4; nf < 8; ++nf) {
            int c = (nf - 4) * 8 + 2 * tig;
            float v0 = (h2 ? d[nf][2] : d[nf][0]) + be[nf - 4][0];
            float v1 = (h2 ? d[nf][3] : d[nf][1]) + be[nf - 4][1];
            seye[r * SE_STRIDE + c]     = v0;
            seye[r * SE_STRIDE + c + 1] = v1;
        }
    }
    __syncthreads();

    // cooperative coalesced writes
    #pragma unroll
    for (int it = 0; it < 4; ++it) {
        int idx  = tid + it * 256;             // 0..1023
        int node = idx >> 5;
        int q    = idx & 31;
        int n    = node0 + node;
        if (n < NN) {
            uint2 v = *(const uint2*)&slin[node * SL_STRIDE + q * 4];
            *(uint2*)&g_hlin[(size_t)n * 128 + q * 4] = v;   // re-read by gather: keep
        }
    }
    // eye half of out: never re-read -> streaming stores (no L2 keep)
    #pragma unroll
    for (int it = 0; it < 8; ++it) {
        int idx = tid + it * 256;              // 0..2047
        int row = idx >> 4;
        int q   = idx & 15;
        int bb  = row >> 5;
        int node = row & 31;
        int n   = node0 + node;
        if (n < NN) {
            float2 v = *(const float2*)&seye[row * SE_STRIDE + q * 2];
            __stcs((float2*)&out[((size_t)bb * NN + n) * 64 + 32 + q * 2], v);
        }
    }
}

// ---------------- scanB: local scan + parallel base; re-zero counts ----------
__global__ __launch_bounds__(1024) void scanB_kernel() {
    __shared__ int wsum[32];
    __shared__ int sbase;
    const int tid = threadIdx.x, lane = tid & 31, wid = tid >> 5;
    const int j = blockIdx.x;

    if (wid == 0) {
        int v = 0;
        for (int k = lane; k < j; k += 32) v += g_blocksums[k];
        #pragma unroll
        for (int d = 16; d > 0; d >>= 1) v += __shfl_down_sync(0xFFFFFFFFu, v, d);
        if (lane == 0) sbase = v;
    }

    int i = j * 1024 + tid;
    int v = (i < NN) ? g_counts[i] : 0;
    int x = v;
    #pragma unroll
    for (int d = 1; d < 32; d <<= 1) {
        int y = __shfl_up_sync(0xFFFFFFFFu, x, d);
        if (lane >= d) x += y;
    }
    if (lane == 31) wsum[wid] = x;
    __syncthreads();
    if (tid < 32) {
        int s = wsum[tid];
        #pragma unroll
        for (int d = 1; d < 32; d <<= 1) {
            int y = __shfl_up_sync(0xFFFFFFFFu, s, d);
            if (tid >= d) s += y;
        }
        wsum[tid] = s;
    }
    __syncthreads();
    int incl = x + (wid ? wsum[wid - 1] : 0) + sbase;
    if (i < NN) {
        g_offsets[i] = incl - v;
        g_counts[i]  = 0;            // leave zero for the next invocation
    }
    if (j == 0 && tid == 0) g_offsets[NN] = EE;
}

// ---------------- CSR scatter: atomic-free, 8 edges/thread (MLP 8) -----------
__global__ __launch_bounds__(256) void scatter_kernel(const int*   __restrict__ rows,
                                                      const int*   __restrict__ cols,
                                                      const float* __restrict__ vals) {
    const int tid = threadIdx.x;
    // scanB has finished reading g_blocksums; reset it for the next invocation
    if (blockIdx.x == 0 && tid < NCHUNK) g_blocksums[tid] = 0;

    int i0 = blockIdx.x * 512 + tid;           // quad index A
    int i1 = i0 + 256;                         // quad index B
    bool v0ok = (i0 < EE / 4);
    bool v1ok = (i1 < EE / 4);

    int4 ra, ca, ka; float4 va;
    int4 rb, cb, kb; float4 vb;
    if (v0ok) {
        ra = ((const int4*)rows)[i0];
        ca = __ldcs(((const int4*)cols) + i0);
        va = __ldcs(((const float4*)vals) + i0);
        ka = __ldcs(((const int4*)g_rank) + i0);
    }
    if (v1ok) {
        rb = ((const int4*)rows)[i1];
        cb = __ldcs(((const int4*)cols) + i1);
        vb = __ldcs(((const float4*)vals) + i1);
        kb = __ldcs(((const int4*)g_rank) + i1);
    }
    if (v0ok) {
        int p0 = g_offsets[ra.x] + ka.x;
        int p1 = g_offsets[ra.y] + ka.y;
        int p2 = g_offsets[ra.z] + ka.z;
        int p3 = g_offsets[ra.w] + ka.w;
        g_csr[p0] = make_int2(ca.x, __float_as_int(va.x));
        g_csr[p1] = make_int2(ca.y, __float_as_int(va.y));
        g_csr[p2] = make_int2(ca.z, __float_as_int(va.z));
        g_csr[p3] = make_int2(ca.w, __float_as_int(va.w));
    }
    if (v1ok) {
        int p0 = g_offsets[rb.x] + kb.x;
        int p1 = g_offsets[rb.y] + kb.y;
        int p2 = g_offsets[rb.z] + kb.z;
        int p3 = g_offsets[rb.w] + kb.w;
        g_csr[p0] = make_int2(cb.x, __float_as_int(vb.x));
        g_csr[p1] = make_int2(cb.y, __float_as_int(vb.y));
        g_csr[p2] = make_int2(cb.z, __float_as_int(vb.z));
        g_csr[p3] = make_int2(cb.w, __float_as_int(vb.w));
    }
}

// ---------------- gather: one warp per node, all 4 batches, fp16 h ----------
__global__ __launch_bounds__(256) void gather_kernel(const float* __restrict__ blin,
                                                     float* __restrict__ out) {
    int n    = (blockIdx.x * blockDim.x + threadIdx.x) >> 5;
    int lane = threadIdx.x & 31;
    if (n >= NN) return;

    int s = g_offsets[n];
    int t = g_offsets[n + 1];

    float a0 = 0.f, a1 = 0.f, a2 = 0.f, a3 = 0.f;
    int e = s;
    for (; e + 4 <= t; e += 4) {
        int2 p0 = g_csr[e];
        int2 p1 = g_csr[e + 1];
        int2 p2 = g_csr[e + 2];
        int2 p3 = g_csr[e + 3];
        uint2 q0 = *(const uint2*)(g_hlin + (size_t)p0.x * 128 + lane * 4);
        uint2 q1 = *(const uint2*)(g_hlin + (size_t)p1.x * 128 + lane * 4);
        uint2 q2 = *(const uint2*)(g_hlin + (size_t)p2.x * 128 + lane * 4);
        uint2 q3 = *(const uint2*)(g_hlin + (size_t)p3.x * 128 + lane * 4);
        float s0 = __int_as_float(p0.y), s1 = __int_as_float(p1.y);
        float s2 = __int_as_float(p2.y), s3 = __int_as_float(p3.y);
        float2 u01, u23;
        u01 = __half22float2(*(__half2*)&q0.x); u23 = __half22float2(*(__half2*)&q0.y);
        a0 += s0 * u01.x; a1 += s0 * u01.y; a2 += s0 * u23.x; a3 += s0 * u23.y;
        u01 = __half22float2(*(__half2*)&q1.x); u23 = __half22float2(*(__half2*)&q1.y);
        a0 += s1 * u01.x; a1 += s1 * u01.y; a2 += s1 * u23.x; a3 += s1 * u23.y;
        u01 = __half22float2(*(__half2*)&q2.x); u23 = __half22float2(*(__half2*)&q2.y);
        a0 += s2 * u01.x; a1 += s2 * u01.y; a2 += s2 * u23.x; a3 += s2 * u23.y;
        u01 = __half22float2(*(__half2*)&q3.x); u23 = __half22float2(*(__half2*)&q3.y);
        a0 += s3 * u01.x; a1 += s3 * u01.y; a2 += s3 * u23.x; a3 += s3 * u23.y;
    }
    for (; e < t; ++e) {
        int2 p = g_csr[e];
        uint2 q = *(const uint2*)(g_hlin + (size_t)p.x * 128 + lane * 4);
        float sv = __int_as_float(p.y);
        float2 u01 = __half22float2(*(__half2*)&q.x);
        float2 u23 = __half22float2(*(__half2*)&q.y);
        a0 += sv * u01.x; a1 += sv * u01.y; a2 += sv * u23.x; a3 += sv * u23.y;
    }

    float bl = blin[lane];
    __stcs(&out[((size_t)0 * NN + n) * 64 + lane], a0 + bl);
    __stcs(&out[((size_t)1 * NN + n) * 64 + lane], a1 + bl);
    __stcs(&out[((size_t)2 * NN + n) * 64 + lane], a2 + bl);
    __stcs(&out[((size_t)3 * NN + n) * 64 + lane], a3 + bl);
}

// ---------------- launch: single stream, 4 kernels ---------------------------
extern "C" void kernel_launch(void* const* d_in, const int* in_sizes, int n_in,
                              void* d_out, int out_size) {
    const float* x    = (const float*)d_in[0];
    const float* vals = (const float*)d_in[1];
    const float* Wlin = (const float*)d_in[2];
    const float* blin = (const float*)d_in[3];
    const float* Weye = (const float*)d_in[4];
    const float* beye = (const float*)d_in[5];
    const int*   rows = (const int*)d_in[6];
    const int*   cols = (const int*)d_in[7];
    float* out = (float*)d_out;
    (void)in_sizes; (void)n_in; (void)out_size;

    // g_counts / g_blocksums are zero on entry (zero-init at load;
    // scanB / scatter re-zero them each call).
    k1_proj_hist_kernel<<<PROJ_BLOCKS + HIST_BLOCKS, 256>>>(
        (const int4*)rows, x, Wlin, Weye, beye, out);
    scanB_kernel<<<NCHUNK, 1024>>>();
    scatter_kernel<<<SCAT_BLOCKS, 256>>>(rows, cols, vals);
    gather_kernel<<<(NN * 32 + 255) / 256, 256>>>(blin, out);
}

// round 15
// speedup vs baseline: 2.0195x; 1.0375x over previous
#include <cuda_runtime.h>
#include <cuda_fp16.h>
#include <cstdint>

// Problem constants (fixed shapes for this dataset)
#define BB   4
#define NN   50000
#define CIN  64
#define EE   800000
#define HALF 32
#define BN   (BB * NN)           // 200000

#define HIST_BLOCKS  782         // ceil(EE/4 / 256), 4 edges/thread
#define SCAT_BLOCKS  391         // ceil(EE/8 / 256), 8 edges/thread
#define PROJ_BLOCKS  1563        // ceil(NN / 32)
#define NCHUNK       49          // ceil(NN/1024)

// ---------------- scratch (device globals; zero-initialized at load) --------
__device__ __half g_hlin[NN * 128];    // [n][ch][b]  half, 12.8 MB (L2-resident)
__device__ int    g_counts[NN];        // kept zero between calls (scanB re-zeros)
__device__ int    g_offsets[NN + 1];
__device__ int    g_rank[EE];          // within-node rank of each edge
__device__ int2   g_csr[EE];           // .x = col, .y = bits(val)
__device__ int    g_blocksums[64];     // kept zero between calls (scatter re-zeros)

// ---------------- mma helper -------------------------------------------------
__device__ __forceinline__ void mma16816(float& d0, float& d1, float& d2, float& d3,
                                         unsigned a0, unsigned a1, unsigned a2, unsigned a3,
                                         unsigned b0, unsigned b1) {
    asm("mma.sync.aligned.m16n8k16.row.col.f32.f16.f16.f32 "
        "{%0,%1,%2,%3}, {%4,%5,%6,%7}, {%8,%9}, {%0,%1,%2,%3};"
        : "+f"(d0), "+f"(d1), "+f"(d2), "+f"(d3)
        : "r"(a0), "r"(a1), "r"(a2), "r"(a3), "r"(b0), "r"(b1));
}

// ---------------- K1: HMMA projection + histogram (block-range fused) --------
// proj tile: 32 nodes x 4 batches (128 A-rows) x 64 outs; 256 threads, 8 warps.
#define XS_STRIDE 72    // halves; frag LDS bank = 4g+tig, conflict-free
#define SL_STRIDE 132   // halves per node in slin
#define SE_STRIDE 34    // floats per row in seye
#define SMEM_BYTES 28672

__global__ __launch_bounds__(256, 3) void k1_proj_hist_kernel(
    const int4*  __restrict__ rows4,
    const float* __restrict__ x,
    const float* __restrict__ Wlin,
    const float* __restrict__ Weye,
    const float* __restrict__ beye,
    float*       __restrict__ out)
{
    __shared__ __align__(16) char sm[SMEM_BYTES];
    const int tid = threadIdx.x;

    if (blockIdx.x >= PROJ_BLOCKS) {
        // ---- histogram + rank recording + chunk sums ----
        int* sh = (int*)sm;
        if (tid < NCHUNK) sh[tid] = 0;
        __syncthreads();

        int i = (blockIdx.x - PROJ_BLOCKS) * 256 + tid;
        if (i < EE / 4) {
            int4 r = rows4[i];
            int4 rk;
            rk.x = atomicAdd(&g_counts[r.x], 1); atomicAdd(&sh[r.x >> 10], 1);
            rk.y = atomicAdd(&g_counts[r.y], 1); atomicAdd(&sh[r.y >> 10], 1);
            rk.z = atomicAdd(&g_counts[r.z], 1); atomicAdd(&sh[r.z >> 10], 1);
            rk.w = atomicAdd(&g_counts[r.w], 1); atomicAdd(&sh[r.w >> 10], 1);
            ((int4*)g_rank)[i] = rk;
        }
        __syncthreads();
        if (tid < NCHUNK && sh[tid]) atomicAdd(&g_blocksums[tid], sh[tid]);
        return;
    }

    // ---- projection ----
    __half* xs = (__half*)sm;                          // [128][XS_STRIDE]
    __half* wt = (__half*)(sm + 128 * XS_STRIDE * 2);  // [64][XS_STRIDE]

    const int node0 = blockIdx.x * 32;

    // Stage x (128 rows = 4b x 32 nodes, 64 ch) + W^T (64 n x 64 k) as fp16.
    // x is read exactly once per call -> streaming loads (evict-first).
    #pragma unroll
    for (int it = 0; it < 12; ++it) {
        int idx = tid + it * 256;                   // 0..3071
        if (idx < 2048) {
            int row = idx >> 4;                     // 0..127
            int c4  = (idx & 15) << 2;
            int b   = row >> 5;
            int node = row & 31;
            int nn  = node0 + node; if (nn >= NN) nn = NN - 1;
            float4 v = __ldcs((const float4*)(x + ((size_t)(b * NN + nn)) * 64 + c4));
            *(__half2*)&xs[row * XS_STRIDE + c4]     = __floats2half2_rn(v.x, v.y);
            *(__half2*)&xs[row * XS_STRIDE + c4 + 2] = __floats2half2_rn(v.z, v.w);
        } else {
            int id2 = idx - 2048;                   // 0..1023
            int row = id2 >> 4;                     // 0..63
            int c4  = (id2 & 15) << 2;
            const float* wsrc = (row < 32) ? (Wlin + row * 64 + c4)
                                           : (Weye + (row - 32) * 64 + c4);
            float4 w = *(const float4*)wsrc;
            *(__half2*)&wt[row * XS_STRIDE + c4]     = __floats2half2_rn(w.x, w.y);
            *(__half2*)&wt[row * XS_STRIDE + c4 + 2] = __floats2half2_rn(w.z, w.w);
        }
    }
    __syncthreads();

    const int warp = tid >> 5;
    const int lane = tid & 31;
    const int g    = lane >> 2;        // 0..7
    const int tig  = lane & 3;         // 0..3
    const int wrow = warp * 16;        // warp's A-row base

    float d[8][4];
    #pragma unroll
    for (int nf = 0; nf < 8; ++nf)
        #pragma unroll
        for (int k = 0; k < 4; ++k) d[nf][k] = 0.f;

    #pragma unroll
    for (int kc = 0; kc < 4; ++kc) {
        const int kb = kc * 16;
        unsigned a0 = *(const unsigned*)&xs[(wrow + g)     * XS_STRIDE + kb + 2 * tig];
        unsigned a1 = *(const unsigned*)&xs[(wrow + g + 8) * XS_STRIDE + kb + 2 * tig];
        unsigned a2 = *(const unsigned*)&xs[(wrow + g)     * XS_STRIDE + kb + 2 * tig + 8];
        unsigned a3 = *(const unsigned*)&xs[(wrow + g + 8) * XS_STRIDE + kb + 2 * tig + 8];
        #pragma unroll
        for (int nf = 0; nf < 8; ++nf) {
            unsigned b0 = *(const unsigned*)&wt[(nf * 8 + g) * XS_STRIDE + kb + 2 * tig];
            unsigned b1 = *(const unsigned*)&wt[(nf * 8 + g) * XS_STRIDE + kb + 2 * tig + 8];
            mma16816(d[nf][0], d[nf][1], d[nf][2], d[nf][3],
                     a0, a1, a2, a3, b0, b1);
        }
    }

    // biases for eye columns (2 per frag)
    float be[4][2];
    #pragma unroll
    for (int nf = 4; nf < 8; ++nf) {
        int oc = nf * 8 + 2 * tig - 32;
        be[nf - 4][0] = __ldg(&beye[oc]);
        be[nf - 4][1] = __ldg(&beye[oc + 1]);
    }

    __syncthreads();   // done reading xs/wt; reuse smem for output staging

    __half* slin = (__half*)sm;                        // [32][SL_STRIDE] halves
    float*  seye = (float*)(sm + 32 * SL_STRIDE * 2);  // [128][SE_STRIDE] floats

    const int b        = warp >> 1;            // batch this warp owns
    const int nodeBase = (warp & 1) * 16;

    #pragma unroll
    for (int h2 = 0; h2 < 2; ++h2) {
        int node = nodeBase + g + 8 * h2;
        int r    = wrow + g + 8 * h2;          // tile row = 32*b + node
        #pragma unroll
        for (int nf = 0; nf < 4; ++nf) {
            int ch = nf * 8 + 2 * tig;
            float v0 = h2 ? d[nf][2] : d[nf][0];
            float v1 = h2 ? d[nf][3] : d[nf][1];
            slin[node * SL_STRIDE + ch * 4 + b]       = __float2half_rn(v0);
            slin[node * SL_STRIDE + (ch + 1) * 4 + b] = __float2half_rn(v1);
        }
        #pragma unroll
        for (int nf = 4; nf < 8; ++nf) {
            int c = (nf - 4) * 8 + 2 * tig;
            float v0 = (h2 ? d[nf][2] : d[nf][0]) + be[nf - 4][0];
            float v1 = (h2 ? d[nf][3] : d[nf][1]) + be[nf - 4][1];
            seye[r * SE_STRIDE + c]     = v0;
            seye[r * SE_STRIDE + c + 1] = v1;
        }
    }
    __syncthreads();

    // cooperative coalesced writes
    #pragma unroll
    for (int it = 0; it < 4; ++it) {
        int idx  = tid + it * 256;             // 0..1023
        int node = idx >> 5;
        int q    = idx & 31;
        int n    = node0 + node;
        if (n < NN) {
            uint2 v = *(const uint2*)&slin[node * SL_STRIDE + q * 4];
            *(uint2*)&g_hlin[(size_t)n * 128 + q * 4] = v;   // re-read by gather: keep
        }
    }
    // eye half of out: never re-read -> streaming stores (no L2 keep)
    #pragma unroll
    for (int it = 0; it < 8; ++it) {
        int idx = tid + it * 256;              // 0..2047
        int row = idx >> 4;
        int q   = idx & 15;
        int bb  = row >> 5;
        int node = row & 31;
        int n   = node0 + node;
        if (n < NN) {
            float2 v = *(const float2*)&seye[row * SE_STRIDE + q * 2];
            __stcs((float2*)&out[((size_t)bb * NN + n) * 64 + 32 + q * 2], v);
        }
    }
}

// ---------------- scanB: local scan + parallel base; re-zero counts ----------
__global__ __launch_bounds__(1024) void scanB_kernel() {
    __shared__ int wsum[32];
    __shared__ int sbase;
    const int tid = threadIdx.x, lane = tid & 31, wid = tid >> 5;
    const int j = blockIdx.x;

    if (wid == 0) {
        int v = 0;
        for (int k = lane; k < j; k += 32) v += g_blocksums[k];
        #pragma unroll
        for (int d = 16; d > 0; d >>= 1) v += __shfl_down_sync(0xFFFFFFFFu, v, d);
        if (lane == 0) sbase = v;
    }

    int i = j * 1024 + tid;
    int v = (i < NN) ? g_counts[i] : 0;
    int x = v;
    #pragma unroll
    for (int d = 1; d < 32; d <<= 1) {
        int y = __shfl_up_sync(0xFFFFFFFFu, x, d);
        if (lane >= d) x += y;
    }
    if (lane == 31) wsum[wid] = x;
    __syncthreads();
    if (tid < 32) {
        int s = wsum[tid];
        #pragma unroll
        for (int d = 1; d < 32; d <<= 1) {
            int y = __shfl_up_sync(0xFFFFFFFFu, s, d);
            if (tid >= d) s += y;
        }
        wsum[tid] = s;
    }
    __syncthreads();
    int incl = x + (wid ? wsum[wid - 1] : 0) + sbase;
    if (i < NN) {
        g_offsets[i] = incl - v;
        g_counts[i]  = 0;            // leave zero for the next invocation
    }
    if (j == 0 && tid == 0) g_offsets[NN] = EE;
}

// ---------------- CSR scatter: atomic-free, 8 edges/thread (MLP 8) -----------
__global__ __launch_bounds__(256) void scatter_kernel(const int*   __restrict__ rows,
                                                      const int*   __restrict__ cols,
                                                      const float* __restrict__ vals) {
    const int tid = threadIdx.x;
    // scanB has finished reading g_blocksums; reset it for the next invocation
    if (blockIdx.x == 0 && tid < NCHUNK) g_blocksums[tid] = 0;

    int i0 = blockIdx.x * 512 + tid;           // quad index A
    int i1 = i0 + 256;                         // quad index B
    bool v0ok = (i0 < EE / 4);
    bool v1ok = (i1 < EE / 4);

    int4 ra, ca, ka; float4 va;
    int4 rb, cb, kb; float4 vb;
    if (v0ok) {
        ra = ((const int4*)rows)[i0];
        ca = __ldcs(((const int4*)cols) + i0);
        va = __ldcs(((const float4*)vals) + i0);
        ka = __ldcs(((const int4*)g_rank) + i0);
    }
    if (v1ok) {
        rb = ((const int4*)rows)[i1];
        cb = __ldcs(((const int4*)cols) + i1);
        vb = __ldcs(((const float4*)vals) + i1);
        kb = __ldcs(((const int4*)g_rank) + i1);
    }
    if (v0ok) {
        int p0 = g_offsets[ra.x] + ka.x;
        int p1 = g_offsets[ra.y] + ka.y;
        int p2 = g_offsets[ra.z] + ka.z;
        int p3 = g_offsets[ra.w] + ka.w;
        g_csr[p0] = make_int2(ca.x, __float_as_int(va.x));
        g_csr[p1] = make_int2(ca.y, __float_as_int(va.y));
        g_csr[p2] = make_int2(ca.z, __float_as_int(va.z));
        g_csr[p3] = make_int2(ca.w, __float_as_int(va.w));
    }
    if (v1ok) {
        int p0 = g_offsets[rb.x] + kb.x;
        int p1 = g_offsets[rb.y] + kb.y;
        int p2 = g_offsets[rb.z] + kb.z;
        int p3 = g_offsets[rb.w] + kb.w;
        g_csr[p0] = make_int2(cb.x, __float_as_int(vb.x));
        g_csr[p1] = make_int2(cb.y, __float_as_int(vb.y));
        g_csr[p2] = make_int2(cb.z, __float_as_int(vb.z));
        g_csr[p3] = make_int2(cb.w, __float_as_int(vb.w));
    }
}

// ---------------- gather: one warp per node, paired CSR loads, plain stores --
__global__ __launch_bounds__(256) void gather_kernel(const float* __restrict__ blin,
                                                     float* __restrict__ out) {
    int n    = (blockIdx.x * blockDim.x + threadIdx.x) >> 5;
    int lane = threadIdx.x & 31;
    if (n >= NN) return;

    int s = g_offsets[n];
    int t = g_offsets[n + 1];

    float a0 = 0.f, a1 = 0.f, a2 = 0.f, a3 = 0.f;
    int e = s;

    // alignment prologue: make e even so int2 pairs are 16B-aligned
    if ((e & 1) && e < t) {
        int2 p = g_csr[e];
        uint2 q = *(const uint2*)(g_hlin + (size_t)p.x * 128 + lane * 4);
        float sv = __int_as_float(p.y);
        float2 u01 = __half22float2(*(__half2*)&q.x);
        float2 u23 = __half22float2(*(__half2*)&q.y);
        a0 += sv * u01.x; a1 += sv * u01.y; a2 += sv * u23.x; a3 += sv * u23.y;
        ++e;
    }

    // main loop: 4 edges per iter, 2x LDG.128 for CSR entries
    for (; e + 4 <= t; e += 4) {
        uint4 pa = *(const uint4*)&g_csr[e];       // edges e, e+1
        uint4 pb = *(const uint4*)&g_csr[e + 2];   // edges e+2, e+3
        uint2 q0 = *(const uint2*)(g_hlin + (size_t)pa.x * 128 + lane * 4);
        uint2 q1 = *(const uint2*)(g_hlin + (size_t)pa.z * 128 + lane * 4);
        uint2 q2 = *(const uint2*)(g_hlin + (size_t)pb.x * 128 + lane * 4);
        uint2 q3 = *(const uint2*)(g_hlin + (size_t)pb.z * 128 + lane * 4);
        float s0 = __uint_as_float(pa.y), s1 = __uint_as_float(pa.w);
        float s2 = __uint_as_float(pb.y), s3 = __uint_as_float(pb.w);
        float2 u01, u23;
        u01 = __half22float2(*(__half2*)&q0.x); u23 = __half22float2(*(__half2*)&q0.y);
        a0 += s0 * u01.x; a1 += s0 * u01.y; a2 += s0 * u23.x; a3 += s0 * u23.y;
        u01 = __half22float2(*(__half2*)&q1.x); u23 = __half22float2(*(__half2*)&q1.y);
        a0 += s1 * u01.x; a1 += s1 * u01.y; a2 += s1 * u23.x; a3 += s1 * u23.y;
        u01 = __half22float2(*(__half2*)&q2.x); u23 = __half22float2(*(__half2*)&q2.y);
        a0 += s2 * u01.x; a1 += s2 * u01.y; a2 += s2 * u23.x; a3 += s2 * u23.y;
        u01 = __half22float2(*(__half2*)&q3.x); u23 = __half22float2(*(__half2*)&q3.y);
        a0 += s3 * u01.x; a1 += s3 * u01.y; a2 += s3 * u23.x; a3 += s3 * u23.y;
    }
    // pair epilogue
    if (e + 2 <= t) {
        uint4 pa = *(const uint4*)&g_csr[e];
        uint2 q0 = *(const uint2*)(g_hlin + (size_t)pa.x * 128 + lane * 4);
        uint2 q1 = *(const uint2*)(g_hlin + (size_t)pa.z * 128 + lane * 4);
        float s0 = __uint_as_float(pa.y), s1 = __uint_as_float(pa.w);
        float2 u01, u23;
        u01 = __half22float2(*(__half2*)&q0.x); u23 = __half22float2(*(__half2*)&q0.y);
        a0 += s0 * u01.x; a1 += s0 * u01.y; a2 += s0 * u23.x; a3 += s0 * u23.y;
        u01 = __half22float2(*(__half2*)&q1.x); u23 = __half22float2(*(__half2*)&q1.y);
        a0 += s1 * u01.x; a1 += s1 * u01.y; a2 += s1 * u23.x; a3 += s1 * u23.y;
        e += 2;
    }
    if (e < t) {
        int2 p = g_csr[e];
        uint2 q = *(const uint2*)(g_hlin + (size_t)p.x * 128 + lane * 4);
        float sv = __int_as_float(p.y);
        float2 u01 = __half22float2(*(__half2*)&q.x);
        float2 u23 = __half22float2(*(__half2*)&q.y);
        a0 += sv * u01.x; a1 += sv * u01.y; a2 += sv * u23.x; a3 += sv * u23.y;
    }

    float bl = blin[lane];
    out[((size_t)0 * NN + n) * 64 + lane] = a0 + bl;
    out[((size_t)1 * NN + n) * 64 + lane] = a1 + bl;
    out[((size_t)2 * NN + n) * 64 + lane] = a2 + bl;
    out[((size_t)3 * NN + n) * 64 + lane] = a3 + bl;
}

// ---------------- launch: single stream, 4 kernels ---------------------------
extern "C" void kernel_launch(void* const* d_in, const int* in_sizes, int n_in,
                              void* d_out, int out_size) {
    const float* x    = (const float*)d_in[0];
    const float* vals = (const float*)d_in[1];
    const float* Wlin = (const float*)d_in[2];
    const float* blin = (const float*)d_in[3];
    const float* Weye = (const float*)d_in[4];
    const float* beye = (const float*)d_in[5];
    const int*   rows = (const int*)d_in[6];
    const int*   cols = (const int*)d_in[7];
    float* out = (float*)d_out;
    (void)in_sizes; (void)n_in; (void)out_size;

    // g_counts / g_blocksums are zero on entry (zero-init at load;
    // scanB / scatter re-zero them each call).
    k1_proj_hist_kernel<<<PROJ_BLOCKS + HIST_BLOCKS, 256>>>(
        (const int4*)rows, x, Wlin, Weye, beye, out);
    scanB_kernel<<<NCHUNK, 1024>>>();
    scatter_kernel<<<SCAT_BLOCKS, 256>>>(rows, cols, vals);
    gather_kernel<<<(NN * 32 + 255) / 256, 256>>>(blin, out);
}

// round 16
// speedup vs baseline: 2.0808x; 1.0304x over previous
#include <cuda_runtime.h>
#include <cuda_fp16.h>
#include <cstdint>

// Problem constants (fixed shapes for this dataset)
#define BB   4
#define NN   50000
#define CIN  64
#define EE   800000
#define HALF 32
#define BN   (BB * NN)           // 200000

#define HIST_BLOCKS  782         // ceil(EE/4 / 256), 4 edges/thread
#define SCAT_BLOCKS  391         // ceil(EE/8 / 256), 8 edges/thread
#define PROJ_BLOCKS  1563        // ceil(NN / 32)
#define NCHUNK       49          // ceil(NN/1024)
#define GATHER_TPB   64          // 2 warps/block -> fine-grain slot recycling
#define GATHER_BLOCKS (NN / 2)   // 25000 blocks, 1 warp per node

// ---------------- scratch (device globals; zero-initialized at load) --------
__device__ __half g_hlin[NN * 128];    // [n][ch][b]  half, 12.8 MB (L2-resident)
__device__ int    g_counts[NN];        // kept zero between calls (scanB re-zeros)
__device__ int    g_offsets[NN + 1];
__device__ int    g_rank[EE];          // within-node rank of each edge
__device__ int2   g_csr[EE];           // .x = col, .y = bits(val)
__device__ int    g_blocksums[64];     // kept zero between calls (scatter re-zeros)

// ---------------- mma helper -------------------------------------------------
__device__ __forceinline__ void mma16816(float& d0, float& d1, float& d2, float& d3,
                                         unsigned a0, unsigned a1, unsigned a2, unsigned a3,
                                         unsigned b0, unsigned b1) {
    asm("mma.sync.aligned.m16n8k16.row.col.f32.f16.f16.f32 "
        "{%0,%1,%2,%3}, {%4,%5,%6,%7}, {%8,%9}, {%0,%1,%2,%3};"
        : "+f"(d0), "+f"(d1), "+f"(d2), "+f"(d3)
        : "r"(a0), "r"(a1), "r"(a2), "r"(a3), "r"(b0), "r"(b1));
}

// ---------------- K1: HMMA projection + histogram (block-range fused) --------
// proj tile: 32 nodes x 4 batches (128 A-rows) x 64 outs; 256 threads, 8 warps.
#define XS_STRIDE 72    // halves; frag LDS bank = 4g+tig, conflict-free
#define SL_STRIDE 132   // halves per node in slin
#define SE_STRIDE 34    // floats per row in seye
#define SMEM_BYTES 28672

__global__ __launch_bounds__(256, 3) void k1_proj_hist_kernel(
    const int4*  __restrict__ rows4,
    const float* __restrict__ x,
    const float* __restrict__ Wlin,
    const float* __restrict__ Weye,
    const float* __restrict__ beye,
    float*       __restrict__ out)
{
    __shared__ __align__(16) char sm[SMEM_BYTES];
    const int tid = threadIdx.x;

    if (blockIdx.x >= PROJ_BLOCKS) {
        // ---- histogram + rank recording + chunk sums ----
        int* sh = (int*)sm;
        if (tid < NCHUNK) sh[tid] = 0;
        __syncthreads();

        int i = (blockIdx.x - PROJ_BLOCKS) * 256 + tid;
        if (i < EE / 4) {
            int4 r = rows4[i];
            int4 rk;
            rk.x = atomicAdd(&g_counts[r.x], 1); atomicAdd(&sh[r.x >> 10], 1);
            rk.y = atomicAdd(&g_counts[r.y], 1); atomicAdd(&sh[r.y >> 10], 1);
            rk.z = atomicAdd(&g_counts[r.z], 1); atomicAdd(&sh[r.z >> 10], 1);
            rk.w = atomicAdd(&g_counts[r.w], 1); atomicAdd(&sh[r.w >> 10], 1);
            ((int4*)g_rank)[i] = rk;
        }
        __syncthreads();
        if (tid < NCHUNK && sh[tid]) atomicAdd(&g_blocksums[tid], sh[tid]);
        return;
    }

    // ---- projection ----
    __half* xs = (__half*)sm;                          // [128][XS_STRIDE]
    __half* wt = (__half*)(sm + 128 * XS_STRIDE * 2);  // [64][XS_STRIDE]

    const int node0 = blockIdx.x * 32;

    // Stage x (128 rows = 4b x 32 nodes, 64 ch) + W^T (64 n x 64 k) as fp16.
    // x is read exactly once per call -> streaming loads (evict-first).
    #pragma unroll
    for (int it = 0; it < 12; ++it) {
        int idx = tid + it * 256;                   // 0..3071
        if (idx < 2048) {
            int row = idx >> 4;                     // 0..127
            int c4  = (idx & 15) << 2;
            int b   = row >> 5;
            int node = row & 31;
            int nn  = node0 + node; if (nn >= NN) nn = NN - 1;
            float4 v = __ldcs((const float4*)(x + ((size_t)(b * NN + nn)) * 64 + c4));
            *(__half2*)&xs[row * XS_STRIDE + c4]     = __floats2half2_rn(v.x, v.y);
            *(__half2*)&xs[row * XS_STRIDE + c4 + 2] = __floats2half2_rn(v.z, v.w);
        } else {
            int id2 = idx - 2048;                   // 0..1023
            int row = id2 >> 4;                     // 0..63
            int c4  = (id2 & 15) << 2;
            const float* wsrc = (row < 32) ? (Wlin + row * 64 + c4)
                                           : (Weye + (row - 32) * 64 + c4);
            float4 w = *(const float4*)wsrc;
            *(__half2*)&wt[row * XS_STRIDE + c4]     = __floats2half2_rn(w.x, w.y);
            *(__half2*)&wt[row * XS_STRIDE + c4 + 2] = __floats2half2_rn(w.z, w.w);
        }
    }
    __syncthreads();

    const int warp = tid >> 5;
    const int lane = tid & 31;
    const int g    = lane >> 2;        // 0..7
    const int tig  = lane & 3;         // 0..3
    const int wrow = warp * 16;        // warp's A-row base

    float d[8][4];
    #pragma unroll
    for (int nf = 0; nf < 8; ++nf)
        #pragma unroll
        for (int k = 0; k < 4; ++k) d[nf][k] = 0.f;

    #pragma unroll
    for (int kc = 0; kc < 4; ++kc) {
        const int kb = kc * 16;
        unsigned a0 = *(const unsigned*)&xs[(wrow + g)     * XS_STRIDE + kb + 2 * tig];
        unsigned a1 = *(const unsigned*)&xs[(wrow + g + 8) * XS_STRIDE + kb + 2 * tig];
        unsigned a2 = *(const unsigned*)&xs[(wrow + g)     * XS_STRIDE + kb + 2 * tig + 8];
        unsigned a3 = *(const unsigned*)&xs[(wrow + g + 8) * XS_STRIDE + kb + 2 * tig + 8];
        #pragma unroll
        for (int nf = 0; nf < 8; ++nf) {
            unsigned b0 = *(const unsigned*)&wt[(nf * 8 + g) * XS_STRIDE + kb + 2 * tig];
            unsigned b1 = *(const unsigned*)&wt[(nf * 8 + g) * XS_STRIDE + kb + 2 * tig + 8];
            mma16816(d[nf][0], d[nf][1], d[nf][2], d[nf][3],
                     a0, a1, a2, a3, b0, b1);
        }
    }

    // biases for eye columns (2 per frag)
    float be[4][2];
    #pragma unroll
    for (int nf = 4; nf < 8; ++nf) {
        int oc = nf * 8 + 2 * tig - 32;
        be[nf - 4][0] = __ldg(&beye[oc]);
        be[nf - 4][1] = __ldg(&beye[oc + 1]);
    }

    __syncthreads();   // done reading xs/wt; reuse smem for output staging

    __half* slin = (__half*)sm;                        // [32][SL_STRIDE] halves
    float*  seye = (float*)(sm + 32 * SL_STRIDE * 2);  // [128][SE_STRIDE] floats

    const int b        = warp >> 1;            // batch this warp owns
    const int nodeBase = (warp & 1) * 16;

    #pragma unroll
    for (int h2 = 0; h2 < 2; ++h2) {
        int node = nodeBase + g + 8 * h2;
        int r    = wrow + g + 8 * h2;          // tile row = 32*b + node
        #pragma unroll
        for (int nf = 0; nf < 4; ++nf) {
            int ch = nf * 8 + 2 * tig;
            float v0 = h2 ? d[nf][2] : d[nf][0];
            float v1 = h2 ? d[nf][3] : d[nf][1];
            slin[node * SL_STRIDE + ch * 4 + b]       = __float2half_rn(v0);
            slin[node * SL_STRIDE + (ch + 1) * 4 + b] = __float2half_rn(v1);
        }
        #pragma unroll
        for (int nf = 4; nf < 8; ++nf) {
            int c = (nf - 4) * 8 + 2 * tig;
            float v0 = (h2 ? d[nf][2] : d[nf][0]) + be[nf - 4][0];
            float v1 = (h2 ? d[nf][3] : d[nf][1]) + be[nf - 4][1];
            seye[r * SE_STRIDE + c]     = v0;
            seye[r * SE_STRIDE + c + 1] = v1;
        }
    }
    __syncthreads();

    // cooperative coalesced writes
    #pragma unroll
    for (int it = 0; it < 4; ++it) {
        int idx  = tid + it * 256;             // 0..1023
        int node = idx >> 5;
        int q    = idx & 31;
        int n    = node0 + node;
        if (n < NN) {
            uint2 v = *(const uint2*)&slin[node * SL_STRIDE + q * 4];
            *(uint2*)&g_hlin[(size_t)n * 128 + q * 4] = v;   // re-read by gather: keep
        }
    }
    // eye half of out: never re-read -> streaming stores (no L2 keep)
    #pragma unroll
    for (int it = 0; it < 8; ++it) {
        int idx = tid + it * 256;              // 0..2047
        int row = idx >> 4;
        int q   = idx & 15;
        int bb  = row >> 5;
        int node = row & 31;
        int n   = node0 + node;
        if (n < NN) {
            float2 v = *(const float2*)&seye[row * SE_STRIDE + q * 2];
            __stcs((float2*)&out[((size_t)bb * NN + n) * 64 + 32 + q * 2], v);
        }
    }
}

// ---------------- scanB: local scan + parallel base; re-zero counts ----------
// PDL: all reads depend on K1's hist -> sync first.
__global__ __launch_bounds__(1024) void scanB_kernel() {
    cudaGridDependencySynchronize();

    __shared__ int wsum[32];
    __shared__ int sbase;
    const int tid = threadIdx.x, lane = tid & 31, wid = tid >> 5;
    const int j = blockIdx.x;

    if (wid == 0) {
        int v = 0;
        for (int k = lane; k < j; k += 32) v += g_blocksums[k];
        #pragma unroll
        for (int d = 16; d > 0; d >>= 1) v += __shfl_down_sync(0xFFFFFFFFu, v, d);
        if (lane == 0) sbase = v;
    }

    int i = j * 1024 + tid;
    int v = (i < NN) ? g_counts[i] : 0;
    int x = v;
    #pragma unroll
    for (int d = 1; d < 32; d <<= 1) {
        int y = __shfl_up_sync(0xFFFFFFFFu, x, d);
        if (lane >= d) x += y;
    }
    if (lane == 31) wsum[wid] = x;
    __syncthreads();
    if (tid < 32) {
        int s = wsum[tid];
        #pragma unroll
        for (int d = 1; d < 32; d <<= 1) {
            int y = __shfl_up_sync(0xFFFFFFFFu, s, d);
            if (tid >= d) s += y;
        }
        wsum[tid] = s;
    }
    __syncthreads();
    int incl = x + (wid ? wsum[wid - 1] : 0) + sbase;
    if (i < NN) {
        g_offsets[i] = incl - v;
        g_counts[i]  = 0;            // leave zero for the next invocation
    }
    if (j == 0 && tid == 0) g_offsets[NN] = EE;
}

// ---------------- CSR scatter: atomic-free, 8 edges/thread (MLP 8) -----------
// PDL: rows/cols/vals are harness inputs (safe pre-sync); g_rank/g_offsets
// and the g_blocksums reset depend on upstream -> after sync.
__global__ __launch_bounds__(256) void scatter_kernel(const int*   __restrict__ rows,
                                                      const int*   __restrict__ cols,
                                                      const float* __restrict__ vals) {
    const int tid = threadIdx.x;

    int i0 = blockIdx.x * 512 + tid;           // quad index A
    int i1 = i0 + 256;                         // quad index B
    bool v0ok = (i0 < EE / 4);
    bool v1ok = (i1 < EE / 4);

    // pre-sync: prefetch pure inputs (overlaps upstream tail)
    int4 ra, ca; float4 va;
    int4 rb, cb; float4 vb;
    if (v0ok) {
        ra = ((const int4*)rows)[i0];
        ca = __ldcs(((const int4*)cols) + i0);
        va = __ldcs(((const float4*)vals) + i0);
    }
    if (v1ok) {
        rb = ((const int4*)rows)[i1];
        cb = __ldcs(((const int4*)cols) + i1);
        vb = __ldcs(((const float4*)vals) + i1);
    }

    cudaGridDependencySynchronize();

    // scanB has finished reading g_blocksums; reset it for the next invocation
    if (blockIdx.x == 0 && tid < NCHUNK) g_blocksums[tid] = 0;

    int4 ka, kb;
    if (v0ok) ka = __ldcs(((const int4*)g_rank) + i0);
    if (v1ok) kb = __ldcs(((const int4*)g_rank) + i1);

    if (v0ok) {
        int p0 = g_offsets[ra.x] + ka.x;
        int p1 = g_offsets[ra.y] + ka.y;
        int p2 = g_offsets[ra.z] + ka.z;
        int p3 = g_offsets[ra.w] + ka.w;
        g_csr[p0] = make_int2(ca.x, __float_as_int(va.x));
        g_csr[p1] = make_int2(ca.y, __float_as_int(va.y));
        g_csr[p2] = make_int2(ca.z, __float_as_int(va.z));
        g_csr[p3] = make_int2(ca.w, __float_as_int(va.w));
    }
    if (v1ok) {
        int p0 = g_offsets[rb.x] + kb.x;
        int p1 = g_offsets[rb.y] + kb.y;
        int p2 = g_offsets[rb.z] + kb.z;
        int p3 = g_offsets[rb.w] + kb.w;
        g_csr[p0] = make_int2(cb.x, __float_as_int(vb.x));
        g_csr[p1] = make_int2(cb.y, __float_as_int(vb.y));
        g_csr[p2] = make_int2(cb.z, __float_as_int(vb.z));
        g_csr[p3] = make_int2(cb.w, __float_as_int(vb.w));
    }
}

// ---------------- gather: one warp per node, 64-thread blocks ----------------
// PDL: blin is a harness input (safe pre-sync); csr/offsets/hlin after sync.
__global__ __launch_bounds__(GATHER_TPB) void gather_kernel(const float* __restrict__ blin,
                                                            float* __restrict__ out) {
    int n    = (blockIdx.x * GATHER_TPB + threadIdx.x) >> 5;
    int lane = threadIdx.x & 31;

    float bl = blin[lane];                 // pre-sync prefetch

    cudaGridDependencySynchronize();

    int s = g_offsets[n];
    int t = g_offsets[n + 1];

    float a0 = 0.f, a1 = 0.f, a2 = 0.f, a3 = 0.f;
    int e = s;

    // alignment prologue: make e even so int2 pairs are 16B-aligned
    if ((e & 1) && e < t) {
        int2 p = g_csr[e];
        uint2 q = *(const uint2*)(g_hlin + (size_t)p.x * 128 + lane * 4);
        float sv = __int_as_float(p.y);
        float2 u01 = __half22float2(*(__half2*)&q.x);
        float2 u23 = __half22float2(*(__half2*)&q.y);
        a0 += sv * u01.x; a1 += sv * u01.y; a2 += sv * u23.x; a3 += sv * u23.y;
        ++e;
    }

    // main loop: 4 edges per iter, 2x LDG.128 for CSR entries
    for (; e + 4 <= t; e += 4) {
        uint4 pa = *(const uint4*)&g_csr[e];       // edges e, e+1
        uint4 pb = *(const uint4*)&g_csr[e + 2];   // edges e+2, e+3
        uint2 q0 = *(const uint2*)(g_hlin + (size_t)pa.x * 128 + lane * 4);
        uint2 q1 = *(const uint2*)(g_hlin + (size_t)pa.z * 128 + lane * 4);
        uint2 q2 = *(const uint2*)(g_hlin + (size_t)pb.x * 128 + lane * 4);
        uint2 q3 = *(const uint2*)(g_hlin + (size_t)pb.z * 128 + lane * 4);
        float s0 = __uint_as_float(pa.y), s1 = __uint_as_float(pa.w);
        float s2 = __uint_as_float(pb.y), s3 = __uint_as_float(pb.w);
        float2 u01, u23;
        u01 = __half22float2(*(__half2*)&q0.x); u23 = __half22float2(*(__half2*)&q0.y);
        a0 += s0 * u01.x; a1 += s0 * u01.y; a2 += s0 * u23.x; a3 += s0 * u23.y;
        u01 = __half22float2(*(__half2*)&q1.x); u23 = __half22float2(*(__half2*)&q1.y);
        a0 += s1 * u01.x; a1 += s1 * u01.y; a2 += s1 * u23.x; a3 += s1 * u23.y;
        u01 = __half22float2(*(__half2*)&q2.x); u23 = __half22float2(*(__half2*)&q2.y);
        a0 += s2 * u01.x; a1 += s2 * u01.y; a2 += s2 * u23.x; a3 += s2 * u23.y;
        u01 = __half22float2(*(__half2*)&q3.x); u23 = __half22float2(*(__half2*)&q3.y);
        a0 += s3 * u01.x; a1 += s3 * u01.y; a2 += s3 * u23.x; a3 += s3 * u23.y;
    }
    // pair epilogue
    if (e + 2 <= t) {
        uint4 pa = *(const uint4*)&g_csr[e];
        uint2 q0 = *(const uint2*)(g_hlin + (size_t)pa.x * 128 + lane * 4);
        uint2 q1 = *(const uint2*)(g_hlin + (size_t)pa.z * 128 + lane * 4);
        float s0 = __uint_as_float(pa.y), s1 = __uint_as_float(pa.w);
        float2 u01, u23;
        u01 = __half22float2(*(__half2*)&q0.x); u23 = __half22float2(*(__half2*)&q0.y);
        a0 += s0 * u01.x; a1 += s0 * u01.y; a2 += s0 * u23.x; a3 += s0 * u23.y;
        u01 = __half22float2(*(__half2*)&q1.x); u23 = __half22float2(*(__half2*)&q1.y);
        a0 += s1 * u01.x; a1 += s1 * u01.y; a2 += s1 * u23.x; a3 += s1 * u23.y;
        e += 2;
    }
    if (e < t) {
        int2 p = g_csr[e];
        uint2 q = *(const uint2*)(g_hlin + (size_t)p.x * 128 + lane * 4);
        float sv = __int_as_float(p.y);
        float2 u01 = __half22float2(*(__half2*)&q.x);
        float2 u23 = __half22float2(*(__half2*)&q.y);
        a0 += sv * u01.x; a1 += sv * u01.y; a2 += sv * u23.x; a3 += sv * u23.y;
    }

    out[((size_t)0 * NN + n) * 64 + lane] = a0 + bl;
    out[((size_t)1 * NN + n) * 64 + lane] = a1 + bl;
    out[((size_t)2 * NN + n) * 64 + lane] = a2 + bl;
    out[((size_t)3 * NN + n) * 64 + lane] = a3 + bl;
}

// ---------------- launch: single stream, PDL-chained kernels -----------------
template <typename... Args>
static inline void launch_pdl(void (*kern)(Args...), dim3 grid, dim3 block,
                              Args... args) {
    cudaLaunchConfig_t cfg = {};
    cfg.gridDim = grid;
    cfg.blockDim = block;
    cudaLaunchAttribute attr[1];
    attr[0].id = cudaLaunchAttributeProgrammaticStreamSerialization;
    attr[0].val.programmaticStreamSerializationAllowed = 1;
    cfg.attrs = attr;
    cfg.numAttrs = 1;
    cudaLaunchKernelEx(&cfg, kern, args...);
}

extern "C" void kernel_launch(void* const* d_in, const int* in_sizes, int n_in,
                              void* d_out, int out_size) {
    const float* x    = (const float*)d_in[0];
    const float* vals = (const float*)d_in[1];
    const float* Wlin = (const float*)d_in[2];
    const float* blin = (const float*)d_in[3];
    const float* Weye = (const float*)d_in[4];
    const float* beye = (const float*)d_in[5];
    const int*   rows = (const int*)d_in[6];
    const int*   cols = (const int*)d_in[7];
    float* out = (float*)d_out;
    (void)in_sizes; (void)n_in; (void)out_size;

    // g_counts / g_blocksums are zero on entry (zero-init at load;
    // scanB / scatter re-zero them each call).
    k1_proj_hist_kernel<<<PROJ_BLOCKS + HIST_BLOCKS, 256>>>(
        (const int4*)rows, x, Wlin, Weye, beye, out);
    launch_pdl(scanB_kernel, dim3(NCHUNK), dim3(1024));
    launch_pdl(scatter_kernel, dim3(SCAT_BLOCKS), dim3(256), rows, cols, vals);
    launch_pdl(gather_kernel, dim3(GATHER_BLOCKS), dim3(GATHER_TPB), blin, out);
}